// round 11
// baseline (speedup 1.0000x reference)
#include <cuda_runtime.h>
#include <cstdint>

#define BB 16
#define NN 16384
#define SS 512
#define NSAMP 16
#define RR2 0.01f
#define NROWS (BB*SS*NSAMP)      // 131072
#define MLP_BLOCKS 512           // NROWS / 256
#define OUT1_OFF (BB*3*SS)       // 24576

#define FPS_CL 8                 // CTAs per batch (cluster size)
#define FPS_THR 512              // threads per CTA
#define FPS_PPT 4                // points per thread
#define FPS_PPC (FPS_THR*FPS_PPT) // 2048 points per CTA

// ---------------- scratch (static device globals; no allocation) -------------
__device__ float4 g_xyz4[BB*NN];          // (x,y,z, x^2+y^2+z^2) - sum NO-FMA
__device__ float4 g_ctr[BB*SS];           // centroid (cx,cy,cz, sn) - sn NO-FMA
__device__ int    g_gidx[BB*SS*NSAMP];
__device__ float  g_y1[NROWS*16];
__device__ float  g_y2[NROWS*16];
__device__ float  g_y3[NROWS*32];
__device__ float  g_part1[MLP_BLOCKS*32];
__device__ float  g_part2[MLP_BLOCKS*32];
__device__ float  g_part3[MLP_BLOCKS*64];
__device__ float  g_scale1[16], g_shift1[16];
__device__ float  g_scale2[16], g_shift2[16];
__device__ float  g_scale3[32], g_shift3[32];

// sum of squares with NO FMA contraction: ((x*x + y*y) + z*z), each op rn
__device__ __forceinline__ float sumsq_nofma(float x, float y, float z) {
    return __fadd_rn(__fadd_rn(__fmul_rn(x, x), __fmul_rn(y, y)), __fmul_rn(z, z));
}

__device__ __forceinline__ uint32_t s2u(const void* p) {
    uint32_t a;
    asm("{ .reg .u64 t; cvta.to.shared.u64 t, %1; cvt.u32.u64 %0, t; }"
        : "=r"(a) : "l"(p));
    return a;
}
__device__ __forceinline__ uint32_t mapa_rank(uint32_t laddr, uint32_t rank) {
    uint32_t r;
    asm("mapa.shared::cluster.u32 %0, %1, %2;" : "=r"(r) : "r"(laddr), "r"(rank));
    return r;
}
__device__ __forceinline__ void st_cl_u64(uint32_t a, unsigned long long v) {
    asm volatile("st.shared::cluster.u64 [%0], %1;" :: "r"(a), "l"(v) : "memory");
}
__device__ __forceinline__ void st_cl_f32(uint32_t a, float v) {
    asm volatile("st.shared::cluster.f32 [%0], %1;" :: "r"(a), "f"(v) : "memory");
}
__device__ __forceinline__ void mbar_arrive_remote(uint32_t remAddr) {
    asm volatile("mbarrier.arrive.release.cluster.shared::cluster.b64 _, [%0];"
                 :: "r"(remAddr) : "memory");
}
__device__ __forceinline__ void mbar_wait_acq_cluster(uint32_t addr, unsigned parity) {
    asm volatile(
        "{\n\t"
        ".reg .pred P;\n\t"
        "WL_%=:\n\t"
        "mbarrier.try_wait.parity.acquire.cluster.shared::cta.b64 P, [%0], %1, 0x989680;\n\t"
        "@P bra.uni WD_%=;\n\t"
        "bra.uni WL_%=;\n\t"
        "WD_%=:\n\t"
        "}"
        :: "r"(addr), "r"(parity) : "memory");
}
__device__ __forceinline__ void cluster_sync_() {
    asm volatile("barrier.cluster.arrive.aligned;" ::: "memory");
    asm volatile("barrier.cluster.wait.aligned;" ::: "memory");
}

// ---------------- K0: build float4 point array ------------------------------
__global__ void k_xyz4(const float* __restrict__ pts) {
    int t = blockIdx.x * blockDim.x + threadIdx.x;
    if (t >= BB*NN) return;
    int b = t / NN, n = t - b*NN;
    const float* P = pts + (size_t)b*6*NN;
    float x = P[n], y = P[NN+n], z = P[2*NN+n];
    g_xyz4[t] = make_float4(x, y, z, sumsq_nofma(x, y, z));
}

// ---------------- K1: FPS, 8-CTA cluster, mbarrier all-to-all ----------------
// Per iteration: REDUX value argmax intra-CTA, atomicMin index tie-break,
// unique winner thread multicasts {key,x,y,z} to all CTAs' double-buffered
// slots and arrives (release.cluster) on every CTA's mbarrier (count=8).
// All threads wait acquire.cluster on the LOCAL barrier (cheap HW sleep),
// then redundantly reduce the 8 candidates. No cluster.sync in the loop.
// Distance expression text identical to the bit-exact R9 version.
__global__ __launch_bounds__(FPS_THR) __cluster_dims__(FPS_CL, 1, 1)
void k_fps(const float* __restrict__ pts) {
    int b    = blockIdx.x >> 3;
    int rank = blockIdx.x & 7;
    const float* P = pts + (size_t)b*6*NN;
    int tid  = threadIdx.x;
    int lane = tid & 31, wid = tid >> 5;

    float px[FPS_PPT], py[FPS_PPT], pz[FPS_PPT], dist[FPS_PPT];
    int nbase = rank * FPS_PPC + tid;
#pragma unroll
    for (int k = 0; k < FPS_PPT; k++) {
        int n = nbase + k*FPS_THR;
        px[k] = P[n]; py[k] = P[NN+n]; pz[k] = P[2*NN+n];
        dist[k] = 1e10f;
    }

    __shared__ unsigned s_w[16];
    __shared__ unsigned s_wv;
    __shared__ int s_idx;
    __shared__ unsigned long long s_ck[2][FPS_CL];
    __shared__ float s_cx[2][FPS_CL], s_cy[2][FPS_CL], s_cz[2][FPS_CL];
    __shared__ unsigned long long s_mbar[2];

    uint32_t a_ck = s2u(&s_ck[0][0]);
    uint32_t a_cx = s2u(&s_cx[0][0]);
    uint32_t a_cy = s2u(&s_cy[0][0]);
    uint32_t a_cz = s2u(&s_cz[0][0]);
    uint32_t a_mb = s2u(&s_mbar[0]);

    if (tid == 0) {
        asm volatile("mbarrier.init.shared.b64 [%0], %1;" :: "r"(a_mb),   "r"((unsigned)FPS_CL) : "memory");
        asm volatile("mbarrier.init.shared.b64 [%0], %1;" :: "r"(a_mb+8), "r"((unsigned)FPS_CL) : "memory");
        s_idx = 0x7fffffff;
    }
    __syncthreads();
    cluster_sync_();   // barriers initialized cluster-wide before any remote arrive

    float cx = P[0], cy = P[NN], cz = P[2*NN];
    if (rank == 0 && tid == 0)
        g_ctr[b*SS] = make_float4(cx, cy, cz, sumsq_nofma(cx, cy, cz));

    unsigned ph[2] = {0u, 0u};
    for (int t = 1; t < SS; t++) {
        int buf = t & 1;
        float tmax = -1.0f;
#pragma unroll
        for (int k = 0; k < FPS_PPT; k++) {
            float dx = px[k]-cx, dy = py[k]-cy, dz = pz[k]-cz;
            float d  = dx*dx + dy*dy + dz*dz;
            float nd = fminf(dist[k], d);
            dist[k] = nd;
            tmax = fmaxf(tmax, nd);
        }
        unsigned vb = __float_as_uint(tmax);          // dist >= 0: bits monotonic
        unsigned vr = __reduce_max_sync(0xffffffffu, vb);
        if (lane == 0) s_w[wid] = vr;
        __syncthreads();
        if (wid == 0) {
            unsigned u = (lane < 16) ? s_w[lane] : 0u;
            u = __reduce_max_sync(0xffffffffu, u);
            if (lane == 0) s_wv = u;
        }
        __syncthreads();
        unsigned wv = s_wv;
        if (vb == wv) {                               // candidate threads (rare)
            int best = 0x7fffffff;
#pragma unroll
            for (int k = 0; k < FPS_PPT; k++)
                if (__float_as_uint(dist[k]) == wv) best = min(best, nbase + k*FPS_THR);
            atomicMin(&s_idx, best);
        }
        __syncthreads();
        int far = s_idx;
        int loc = far - rank*FPS_PPC;
        if (loc >= 0 && loc < FPS_PPC && (loc & (FPS_THR-1)) == tid) {
            // unique owner thread in this CTA: post candidate + arrive everywhere
            int kk = loc >> 9;                        // /FPS_THR
            float x = 0.f, y = 0.f, z = 0.f;
#pragma unroll
            for (int k = 0; k < FPS_PPT; k++)
                if (k == kk) { x = px[k]; y = py[k]; z = pz[k]; }
            unsigned long long key =
                ((unsigned long long)wv << 32) |
                (unsigned)(0xFFFFFFFFu - (unsigned)far);
            uint32_t off = (uint32_t)(buf*FPS_CL + rank);
#pragma unroll
            for (uint32_t r = 0; r < FPS_CL; r++) {
                st_cl_u64(mapa_rank(a_ck + off*8, r), key);
                st_cl_f32(mapa_rank(a_cx + off*4, r), x);
                st_cl_f32(mapa_rank(a_cy + off*4, r), y);
                st_cl_f32(mapa_rank(a_cz + off*4, r), z);
            }
#pragma unroll
            for (uint32_t r = 0; r < FPS_CL; r++)
                mbar_arrive_remote(mapa_rank(a_mb + (uint32_t)buf*8, r));
        }
        mbar_wait_acq_cluster(a_mb + (uint32_t)buf*8, ph[buf]);
        ph[buf] ^= 1u;
        if (tid == 0) s_idx = 0x7fffffff;             // next use ordered by next bars
        // all threads reduce the 8 candidates identically (deterministic)
        unsigned long long wk = s_ck[buf][0];
        float wx = s_cx[buf][0], wy = s_cy[buf][0], wz = s_cz[buf][0];
#pragma unroll
        for (int r = 1; r < FPS_CL; r++) {
            unsigned long long kk2 = s_ck[buf][r];
            if (kk2 > wk) { wk = kk2; wx = s_cx[buf][r]; wy = s_cy[buf][r]; wz = s_cz[buf][r]; }
        }
        cx = wx; cy = wy; cz = wz;
        if (rank == 0 && tid == 0)
            g_ctr[b*SS + t] = make_float4(wx, wy, wz, sumsq_nofma(wx, wy, wz));
    }
    cluster_sync_();   // no CTA exits while peers may still be reading
}

// ---------------- K2: ball query (one warp per 8 groups) ---------------------
__global__ __launch_bounds__(256) void k_ball() {
    int w    = threadIdx.x >> 5;
    int lane = threadIdx.x & 31;
    int gbase = blockIdx.x * 64 + w * 8;      // 64 groups per block, same batch
    int b = gbase >> 9;

    __shared__ int sbuf[8][8][16];

    float4 c[8]; int cnt[8];
#pragma unroll
    for (int j = 0; j < 8; j++) { c[j] = g_ctr[gbase + j]; cnt[j] = 0; }

    const float4* __restrict__ Q = g_xyz4 + (size_t)b*NN;
    unsigned lmask = (1u << lane) - 1u;

    float4 q = Q[lane];
    for (int n0 = 0; n0 < NN; n0 += 32) {
        float4 qn = Q[(n0 + 32 + lane) & (NN - 1)];
        int n = n0 + lane;
#pragma unroll
        for (int j = 0; j < 8; j++) {
            float d0  = __fmul_rn(c[j].x, q.x);
            float d1  = fmaf(c[j].y, q.y, d0);
            float dot = fmaf(c[j].z, q.z, d1);
            float sq  = __fsub_rn(__fadd_rn(c[j].w, q.w), __fmul_rn(2.0f, dot));
            bool pred = !(sq > RR2);
            unsigned m = __ballot_sync(0xffffffffu, pred);
            if (m) {
                int pos = cnt[j] + __popc(m & lmask);
                if (pred && pos < 16) sbuf[w][j][pos] = n;
                cnt[j] += __popc(m);
            }
        }
        q = qn;
    }
    __syncwarp();
#pragma unroll
    for (int j = 0; j < 8; j++) {
        int cj = cnt[j];
        int first = sbuf[w][j][0];
        if (lane < 16) {
            int v = (lane < cj) ? sbuf[w][j][lane] : first;
            g_gidx[(gbase + j)*16 + lane] = v;
        }
    }
}

// ------------- deterministic per-block stat reduction ------------------------
template<int NCH>
__device__ __forceinline__ void stat_reduce(float* ls, float* lq, float* part) {
    __shared__ float ss[8][NCH], sq2[8][NCH];
    int wid = threadIdx.x >> 5, lane = threadIdx.x & 31;
#pragma unroll
    for (int c = 0; c < NCH; c++) {
        float v = ls[c], q = lq[c];
#pragma unroll
        for (int off = 16; off; off >>= 1) {
            v += __shfl_down_sync(0xffffffffu, v, off);
            q += __shfl_down_sync(0xffffffffu, q, off);
        }
        if (lane == 0) { ss[wid][c] = v; sq2[wid][c] = q; }
    }
    __syncthreads();
    if (threadIdx.x < NCH) {
        float v = 0.f, q = 0.f;
#pragma unroll
        for (int ww = 0; ww < 8; ww++) { v += ss[ww][threadIdx.x]; q += sq2[ww][threadIdx.x]; }
        part[blockIdx.x*(2*NCH) + threadIdx.x]       = v;
        part[blockIdx.x*(2*NCH) + NCH + threadIdx.x] = q;
    }
}

template<int NCH>
__device__ __forceinline__ void stat_final(const float* part, const float* g,
                                           const float* be, float* scale, float* shift) {
    int c = threadIdx.x;
    if (c >= NCH) return;
    float s = 0.f, q = 0.f;
    for (int i = 0; i < MLP_BLOCKS; i++) {
        s += part[i*2*NCH + c];
        q += part[i*2*NCH + NCH + c];
    }
    float inv  = 1.0f / (float)NROWS;
    float mean = s * inv;
    float var  = q * inv - mean*mean;
    float rstd = rsqrtf(var + 1e-5f);
    float a = g[c] * rstd;
    scale[c] = a;
    shift[c] = be[c] - mean * a;
}

// ---------------- K3: gather + linear1 (fp32) + stats ------------------------
__global__ __launch_bounds__(256) void k_mlp1(const float* __restrict__ pts,
                                              const float* __restrict__ w1,
                                              const float* __restrict__ b1) {
    int row = blockIdx.x * 256 + threadIdx.x;   // < NROWS
    int g = row >> 4;
    int b = g >> 9;
    int gi = g_gidx[row];
    gi = min(gi, NN-1);
    float4 p = g_xyz4[(size_t)b*NN + gi];
    float4 c = g_ctr[g];
    const float* PNr = pts + (size_t)b*6*NN + 3*NN;
    float f[6];
    f[0] = p.x - c.x; f[1] = p.y - c.y; f[2] = p.z - c.z;
    f[3] = PNr[gi]; f[4] = PNr[NN+gi]; f[5] = PNr[2*NN+gi];

    float ls[16], lq[16];
    float4* O4 = (float4*)(g_y1 + (size_t)row*16);
#pragma unroll
    for (int o4 = 0; o4 < 4; o4++) {
        float4 yv;
        float* yp = (float*)&yv;
#pragma unroll
        for (int oo = 0; oo < 4; oo++) {
            int o = o4*4 + oo;
            float y = 0.f;
#pragma unroll
            for (int cc = 0; cc < 6; cc++) y = fmaf(f[cc], w1[o*6 + cc], y);
            y += b1[o];
            yp[oo] = y;
            ls[o] = y; lq[o] = y*y;
        }
        O4[o4] = yv;
    }
    stat_reduce<16>(ls, lq, g_part1);
}

__global__ void k_stats1(const float* g, const float* be) {
    stat_final<16>(g_part1, g, be, g_scale1, g_shift1);
}

// ---------------- K4: bnrelu1 + linear2 (fp32) + stats -----------------------
__global__ __launch_bounds__(256) void k_mlp2(const float* __restrict__ w2,
                                              const float* __restrict__ b2) {
    int row = blockIdx.x * 256 + threadIdx.x;
    float h[16];
    const float4* Y4 = (const float4*)(g_y1 + (size_t)row*16);
#pragma unroll
    for (int k4 = 0; k4 < 4; k4++) {
        float4 yv = Y4[k4];
        const float* yp = (const float*)&yv;
#pragma unroll
        for (int kk = 0; kk < 4; kk++) {
            int k = k4*4 + kk;
            h[k] = fmaxf(0.f, yp[kk]*g_scale1[k] + g_shift1[k]);
        }
    }

    float ls[16], lq[16];
    float4* O4 = (float4*)(g_y2 + (size_t)row*16);
#pragma unroll
    for (int o4 = 0; o4 < 4; o4++) {
        float4 yv;
        float* yp = (float*)&yv;
#pragma unroll
        for (int oo = 0; oo < 4; oo++) {
            int o = o4*4 + oo;
            float y = 0.f;
#pragma unroll
            for (int k = 0; k < 16; k++) y = fmaf(h[k], w2[o*16 + k], y);
            y += b2[o];
            yp[oo] = y;
            ls[o] = y; lq[o] = y*y;
        }
        O4[o4] = yv;
    }
    stat_reduce<16>(ls, lq, g_part2);
}

__global__ void k_stats2(const float* g, const float* be) {
    stat_final<16>(g_part2, g, be, g_scale2, g_shift2);
}

// ---------------- K5: bnrelu2 + linear3 (fp32) + stats -----------------------
__global__ __launch_bounds__(256) void k_mlp3(const float* __restrict__ w3,
                                              const float* __restrict__ b3) {
    int row = blockIdx.x * 256 + threadIdx.x;
    float h[16];
    const float4* Y4 = (const float4*)(g_y2 + (size_t)row*16);
#pragma unroll
    for (int k4 = 0; k4 < 4; k4++) {
        float4 yv = Y4[k4];
        const float* yp = (const float*)&yv;
#pragma unroll
        for (int kk = 0; kk < 4; kk++) {
            int k = k4*4 + kk;
            h[k] = fmaxf(0.f, yp[kk]*g_scale2[k] + g_shift2[k]);
        }
    }

    float ls[32], lq[32];
    float4* O4 = (float4*)(g_y3 + (size_t)row*32);
#pragma unroll
    for (int o4 = 0; o4 < 8; o4++) {
        float4 yv;
        float* yp = (float*)&yv;
#pragma unroll
        for (int oo = 0; oo < 4; oo++) {
            int o = o4*4 + oo;
            float y = 0.f;
#pragma unroll
            for (int k = 0; k < 16; k++) y = fmaf(h[k], w3[o*16 + k], y);
            y += b3[o];
            yp[oo] = y;
            ls[o] = y; lq[o] = y*y;
        }
        O4[o4] = yv;
    }
    stat_reduce<32>(ls, lq, g_part3);
}

__global__ void k_stats3(const float* g, const float* be) {
    stat_final<32>(g_part3, g, be, g_scale3, g_shift3);
}

// ---------------- K6: bnrelu3 + max over nsample + transposed store ----------
__global__ void k_max(float* __restrict__ out) {
    int t = blockIdx.x * 256 + threadIdx.x;   // BB*SS*32
    if (t >= BB*SS*32) return;
    int o = t & 31;
    int g = t >> 5;                // b*SS + s
    int b = g >> 9, s = g & 511;
    float a = g_scale3[o], sh = g_shift3[o];
    const float* Y = g_y3 + (size_t)g*16*32 + o;
    float m = 0.0f;                // relu output >= 0
#pragma unroll
    for (int j = 0; j < 16; j++) {
        float h = fmaxf(0.f, Y[j*32]*a + sh);
        m = fmaxf(m, h);
    }
    out[OUT1_OFF + ((b*32 + o) << 9) + s] = m;
}

// ---------------- K7: new_xyz output (B,3,S) ---------------------------------
__global__ void k_out0(float* __restrict__ out) {
    int t = blockIdx.x * 256 + threadIdx.x;   // BB*3*SS
    if (t >= BB*3*SS) return;
    int b = t / (3*SS);
    int r = t - b*3*SS;
    int c = r >> 9, s = r & 511;
    float4 ct = g_ctr[b*SS + s];
    float v = (c == 0) ? ct.x : (c == 1) ? ct.y : ct.z;
    out[t] = v;
}

// ---------------- launcher ---------------------------------------------------
extern "C" void kernel_launch(void* const* d_in, const int* in_sizes, int n_in,
                              void* d_out, int out_size) {
    const float* pts = (const float*)d_in[0];
    const float* w1  = (const float*)d_in[1];
    const float* b1  = (const float*)d_in[2];
    const float* g1  = (const float*)d_in[3];
    const float* be1 = (const float*)d_in[4];
    const float* w2  = (const float*)d_in[5];
    const float* b2  = (const float*)d_in[6];
    const float* g2  = (const float*)d_in[7];
    const float* be2 = (const float*)d_in[8];
    const float* w3  = (const float*)d_in[9];
    const float* b3  = (const float*)d_in[10];
    const float* g3  = (const float*)d_in[11];
    const float* be3 = (const float*)d_in[12];
    float* out = (float*)d_out;

    k_xyz4<<<(BB*NN + 255)/256, 256>>>(pts);
    k_fps<<<BB*FPS_CL, FPS_THR>>>(pts);
    k_ball<<<(BB*SS)/64, 256>>>();
    k_mlp1<<<MLP_BLOCKS, 256>>>(pts, w1, b1);
    k_stats1<<<1, 32>>>(g1, be1);
    k_mlp2<<<MLP_BLOCKS, 256>>>(w2, b2);
    k_stats2<<<1, 32>>>(g2, be2);
    k_mlp3<<<MLP_BLOCKS, 256>>>(w3, b3);
    k_stats3<<<1, 32>>>(g3, be3);
    k_max<<<(BB*SS*32 + 255)/256, 256>>>(out);
    k_out0<<<(BB*3*SS + 255)/256, 256>>>(out);
}

// round 14
// speedup vs baseline: 1.7342x; 1.7342x over previous
#include <cuda_runtime.h>
#include <cstdint>

#define BB 16
#define NN 16384
#define SS 512
#define NSAMP 16
#define RR2 0.01f
#define NROWS (BB*SS*NSAMP)      // 131072
#define MLP_BLOCKS 512           // NROWS / 256
#define OUT1_OFF (BB*3*SS)       // 24576

#define FPS_THR 512
#define FPS_PPT 32               // points per thread (512*32 = 16384)
#define FPS_SMEM (NN*8 + NN*4)   // float2 xy + float z = 196608 bytes

// ---------------- scratch (static device globals; no allocation) -------------
__device__ float4 g_xyz4[BB*NN];          // (x,y,z, x^2+y^2+z^2) - sum NO-FMA
__device__ float4 g_ctr[BB*SS];           // centroid (cx,cy,cz, sn) - sn NO-FMA
__device__ int    g_gidx[BB*SS*NSAMP];
__device__ float  g_y1[NROWS*16];
__device__ float  g_y2[NROWS*16];
__device__ float  g_y3[NROWS*32];
__device__ float  g_part1[MLP_BLOCKS*32];
__device__ float  g_part2[MLP_BLOCKS*32];
__device__ float  g_part3[MLP_BLOCKS*64];
__device__ float  g_scale1[16], g_shift1[16];
__device__ float  g_scale2[16], g_shift2[16];
__device__ float  g_scale3[32], g_shift3[32];

// sum of squares with NO FMA contraction: ((x*x + y*y) + z*z), each op rn
__device__ __forceinline__ float sumsq_nofma(float x, float y, float z) {
    return __fadd_rn(__fadd_rn(__fmul_rn(x, x), __fmul_rn(y, y)), __fmul_rn(z, z));
}

// ---------------- K0: build float4 point array ------------------------------
__global__ void k_xyz4(const float* __restrict__ pts) {
    int t = blockIdx.x * blockDim.x + threadIdx.x;
    if (t >= BB*NN) return;
    int b = t / NN, n = t - b*NN;
    const float* P = pts + (size_t)b*6*NN;
    float x = P[n], y = P[NN+n], z = P[2*NN+n];
    g_xyz4[t] = make_float4(x, y, z, sumsq_nofma(x, y, z));
}

// ---------------- K1: FPS (one CTA per batch, smem-resident points) ----------
// 512 threads, 32 pts/thread. Coords x,y live in smem (streamed via LDS.64),
// z and running dist live in registers -> no register spills (the R9 1024-thr
// version spilled ~30 regs/thread and paid LDL every iteration).
// Packed u64 key (dist bits desc, index asc tie-break) -> 5-lvl warp shfl ->
// 16 keys -> warp0 4-lvl shfl. 2 barriers/iter. Centroid recovered by
// broadcast LDS from sxy/sz[far] (no winner-publish step).
// Distance expression text identical to the bit-exact R9 version.
__global__ __launch_bounds__(FPS_THR) void k_fps(const float* __restrict__ pts) {
    extern __shared__ char dyn[];
    float2* sxy = (float2*)dyn;                 // 128 KB
    float*  sz  = (float*)(dyn + NN*8);         // 64 KB (lookup only)
    int b = blockIdx.x;
    const float* P = pts + (size_t)b*6*NN;
    int tid = threadIdx.x;
    int lane = tid & 31, wid = tid >> 5;

    float pz_[FPS_PPT], dist[FPS_PPT];
#pragma unroll
    for (int k = 0; k < FPS_PPT; k++) {
        int n = tid + k*FPS_THR;
        float x = P[n], y = P[NN+n], z = P[2*NN+n];
        sxy[n] = make_float2(x, y);
        sz[n]  = z;
        pz_[k] = z;
        dist[k] = 1e10f;
    }

    __shared__ unsigned long long s_key[16];
    __shared__ unsigned long long s_res;

    __syncthreads();

    // iteration 0: centroid = point 0
    float2 c0 = sxy[0];
    float cx = c0.x, cy = c0.y, cz = sz[0];
    if (tid == 0)
        g_ctr[b*SS] = make_float4(cx, cy, cz, sumsq_nofma(cx, cy, cz));

    for (int t = 1; t < SS; t++) {
        float bv = -1.0f; int bi = 0;
#pragma unroll
        for (int k = 0; k < FPS_PPT; k++) {
            float2 xy = sxy[tid + k*FPS_THR];
            float dx = xy.x-cx, dy = xy.y-cy, dz = pz_[k]-cz;
            float d  = dx*dx + dy*dy + dz*dz;
            float nd = fminf(dist[k], d);
            dist[k] = nd;
            if (nd > bv) { bv = nd; bi = tid + (k << 9); }
        }
        unsigned long long key =
            ((unsigned long long)__float_as_uint(bv) << 32) |
            (unsigned)(0xFFFFFFFFu - (unsigned)bi);
#pragma unroll
        for (int off = 16; off; off >>= 1) {
            unsigned long long o = __shfl_xor_sync(0xffffffffu, key, off);
            if (o > key) key = o;
        }
        if (lane == 0) s_key[wid] = key;
        __syncthreads();                           // B1
        if (wid == 0) {
            unsigned long long u = (lane < 16) ? s_key[lane] : 0ULL;
#pragma unroll
            for (int off = 8; off; off >>= 1) {
                unsigned long long o = __shfl_xor_sync(0xffffffffu, u, off);
                if (o > u) u = o;
            }
            if (lane == 0) s_res = u;
        }
        __syncthreads();                           // B2
        int far = (int)(0xFFFFFFFFu - (unsigned)s_res);
        float2 cc = sxy[far];                      // broadcast LDS
        cx = cc.x; cy = cc.y; cz = sz[far];
        if (tid == 0)
            g_ctr[b*SS + t] = make_float4(cx, cy, cz, sumsq_nofma(cx, cy, cz));
    }
}

// ---------------- K2: ball query (one warp per 8 groups) ---------------------
__global__ __launch_bounds__(256) void k_ball() {
    int w    = threadIdx.x >> 5;
    int lane = threadIdx.x & 31;
    int gbase = blockIdx.x * 64 + w * 8;      // 64 groups per block, same batch
    int b = gbase >> 9;

    __shared__ int sbuf[8][8][16];

    float4 c[8]; int cnt[8];
#pragma unroll
    for (int j = 0; j < 8; j++) { c[j] = g_ctr[gbase + j]; cnt[j] = 0; }

    const float4* __restrict__ Q = g_xyz4 + (size_t)b*NN;
    unsigned lmask = (1u << lane) - 1u;

    float4 q = Q[lane];
    for (int n0 = 0; n0 < NN; n0 += 32) {
        float4 qn = Q[(n0 + 32 + lane) & (NN - 1)];
        int n = n0 + lane;
#pragma unroll
        for (int j = 0; j < 8; j++) {
            float d0  = __fmul_rn(c[j].x, q.x);
            float d1  = fmaf(c[j].y, q.y, d0);
            float dot = fmaf(c[j].z, q.z, d1);
            float sq  = __fsub_rn(__fadd_rn(c[j].w, q.w), __fmul_rn(2.0f, dot));
            bool pred = !(sq > RR2);
            unsigned m = __ballot_sync(0xffffffffu, pred);
            if (m) {
                int pos = cnt[j] + __popc(m & lmask);
                if (pred && pos < 16) sbuf[w][j][pos] = n;
                cnt[j] += __popc(m);
            }
        }
        q = qn;
    }
    __syncwarp();
#pragma unroll
    for (int j = 0; j < 8; j++) {
        int cj = cnt[j];
        int first = sbuf[w][j][0];
        if (lane < 16) {
            int v = (lane < cj) ? sbuf[w][j][lane] : first;
            g_gidx[(gbase + j)*16 + lane] = v;
        }
    }
}

// ------------- deterministic per-block stat reduction ------------------------
template<int NCH>
__device__ __forceinline__ void stat_reduce(float* ls, float* lq, float* part) {
    __shared__ float ss[8][NCH], sq2[8][NCH];
    int wid = threadIdx.x >> 5, lane = threadIdx.x & 31;
#pragma unroll
    for (int c = 0; c < NCH; c++) {
        float v = ls[c], q = lq[c];
#pragma unroll
        for (int off = 16; off; off >>= 1) {
            v += __shfl_down_sync(0xffffffffu, v, off);
            q += __shfl_down_sync(0xffffffffu, q, off);
        }
        if (lane == 0) { ss[wid][c] = v; sq2[wid][c] = q; }
    }
    __syncthreads();
    if (threadIdx.x < NCH) {
        float v = 0.f, q = 0.f;
#pragma unroll
        for (int ww = 0; ww < 8; ww++) { v += ss[ww][threadIdx.x]; q += sq2[ww][threadIdx.x]; }
        part[blockIdx.x*(2*NCH) + threadIdx.x]       = v;
        part[blockIdx.x*(2*NCH) + NCH + threadIdx.x] = q;
    }
}

template<int NCH>
__device__ __forceinline__ void stat_final(const float* part, const float* g,
                                           const float* be, float* scale, float* shift) {
    int c = threadIdx.x;
    if (c >= NCH) return;
    float s = 0.f, q = 0.f;
    for (int i = 0; i < MLP_BLOCKS; i++) {
        s += part[i*2*NCH + c];
        q += part[i*2*NCH + NCH + c];
    }
    float inv  = 1.0f / (float)NROWS;
    float mean = s * inv;
    float var  = q * inv - mean*mean;
    float rstd = rsqrtf(var + 1e-5f);
    float a = g[c] * rstd;
    scale[c] = a;
    shift[c] = be[c] - mean * a;
}

// ---------------- K3: gather + linear1 (fp32) + stats ------------------------
__global__ __launch_bounds__(256) void k_mlp1(const float* __restrict__ pts,
                                              const float* __restrict__ w1,
                                              const float* __restrict__ b1) {
    int row = blockIdx.x * 256 + threadIdx.x;   // < NROWS
    int g = row >> 4;
    int b = g >> 9;
    int gi = g_gidx[row];
    gi = min(gi, NN-1);
    float4 p = g_xyz4[(size_t)b*NN + gi];
    float4 c = g_ctr[g];
    const float* PNr = pts + (size_t)b*6*NN + 3*NN;
    float f[6];
    f[0] = p.x - c.x; f[1] = p.y - c.y; f[2] = p.z - c.z;
    f[3] = PNr[gi]; f[4] = PNr[NN+gi]; f[5] = PNr[2*NN+gi];

    float ls[16], lq[16];
    float4* O4 = (float4*)(g_y1 + (size_t)row*16);
#pragma unroll
    for (int o4 = 0; o4 < 4; o4++) {
        float4 yv;
        float* yp = (float*)&yv;
#pragma unroll
        for (int oo = 0; oo < 4; oo++) {
            int o = o4*4 + oo;
            float y = 0.f;
#pragma unroll
            for (int cc = 0; cc < 6; cc++) y = fmaf(f[cc], w1[o*6 + cc], y);
            y += b1[o];
            yp[oo] = y;
            ls[o] = y; lq[o] = y*y;
        }
        O4[o4] = yv;
    }
    stat_reduce<16>(ls, lq, g_part1);
}

__global__ void k_stats1(const float* g, const float* be) {
    stat_final<16>(g_part1, g, be, g_scale1, g_shift1);
}

// ---------------- K4: bnrelu1 + linear2 (fp32) + stats -----------------------
__global__ __launch_bounds__(256) void k_mlp2(const float* __restrict__ w2,
                                              const float* __restrict__ b2) {
    int row = blockIdx.x * 256 + threadIdx.x;
    float h[16];
    const float4* Y4 = (const float4*)(g_y1 + (size_t)row*16);
#pragma unroll
    for (int k4 = 0; k4 < 4; k4++) {
        float4 yv = Y4[k4];
        const float* yp = (const float*)&yv;
#pragma unroll
        for (int kk = 0; kk < 4; kk++) {
            int k = k4*4 + kk;
            h[k] = fmaxf(0.f, yp[kk]*g_scale1[k] + g_shift1[k]);
        }
    }

    float ls[16], lq[16];
    float4* O4 = (float4*)(g_y2 + (size_t)row*16);
#pragma unroll
    for (int o4 = 0; o4 < 4; o4++) {
        float4 yv;
        float* yp = (float*)&yv;
#pragma unroll
        for (int oo = 0; oo < 4; oo++) {
            int o = o4*4 + oo;
            float y = 0.f;
#pragma unroll
            for (int k = 0; k < 16; k++) y = fmaf(h[k], w2[o*16 + k], y);
            y += b2[o];
            yp[oo] = y;
            ls[o] = y; lq[o] = y*y;
        }
        O4[o4] = yv;
    }
    stat_reduce<16>(ls, lq, g_part2);
}

__global__ void k_stats2(const float* g, const float* be) {
    stat_final<16>(g_part2, g, be, g_scale2, g_shift2);
}

// ---------------- K5: bnrelu2 + linear3 (fp32) + stats -----------------------
__global__ __launch_bounds__(256) void k_mlp3(const float* __restrict__ w3,
                                              const float* __restrict__ b3) {
    int row = blockIdx.x * 256 + threadIdx.x;
    float h[16];
    const float4* Y4 = (const float4*)(g_y2 + (size_t)row*16);
#pragma unroll
    for (int k4 = 0; k4 < 4; k4++) {
        float4 yv = Y4[k4];
        const float* yp = (const float*)&yv;
#pragma unroll
        for (int kk = 0; kk < 4; kk++) {
            int k = k4*4 + kk;
            h[k] = fmaxf(0.f, yp[kk]*g_scale2[k] + g_shift2[k]);
        }
    }

    float ls[32], lq[32];
    float4* O4 = (float4*)(g_y3 + (size_t)row*32);
#pragma unroll
    for (int o4 = 0; o4 < 8; o4++) {
        float4 yv;
        float* yp = (float*)&yv;
#pragma unroll
        for (int oo = 0; oo < 4; oo++) {
            int o = o4*4 + oo;
            float y = 0.f;
#pragma unroll
            for (int k = 0; k < 16; k++) y = fmaf(h[k], w3[o*16 + k], y);
            y += b3[o];
            yp[oo] = y;
            ls[o] = y; lq[o] = y*y;
        }
        O4[o4] = yv;
    }
    stat_reduce<32>(ls, lq, g_part3);
}

__global__ void k_stats3(const float* g, const float* be) {
    stat_final<32>(g_part3, g, be, g_scale3, g_shift3);
}

// ---------------- K6: bnrelu3 + max over nsample + transposed store ----------
__global__ void k_max(float* __restrict__ out) {
    int t = blockIdx.x * 256 + threadIdx.x;   // BB*SS*32
    if (t >= BB*SS*32) return;
    int o = t & 31;
    int g = t >> 5;                // b*SS + s
    int b = g >> 9, s = g & 511;
    float a = g_scale3[o], sh = g_shift3[o];
    const float* Y = g_y3 + (size_t)g*16*32 + o;
    float m = 0.0f;                // relu output >= 0
#pragma unroll
    for (int j = 0; j < 16; j++) {
        float h = fmaxf(0.f, Y[j*32]*a + sh);
        m = fmaxf(m, h);
    }
    out[OUT1_OFF + ((b*32 + o) << 9) + s] = m;
}

// ---------------- K7: new_xyz output (B,3,S) ---------------------------------
__global__ void k_out0(float* __restrict__ out) {
    int t = blockIdx.x * 256 + threadIdx.x;   // BB*3*SS
    if (t >= BB*3*SS) return;
    int b = t / (3*SS);
    int r = t - b*3*SS;
    int c = r >> 9, s = r & 511;
    float4 ct = g_ctr[b*SS + s];
    float v = (c == 0) ? ct.x : (c == 1) ? ct.y : ct.z;
    out[t] = v;
}

// ---------------- launcher ---------------------------------------------------
extern "C" void kernel_launch(void* const* d_in, const int* in_sizes, int n_in,
                              void* d_out, int out_size) {
    const float* pts = (const float*)d_in[0];
    const float* w1  = (const float*)d_in[1];
    const float* b1  = (const float*)d_in[2];
    const float* g1  = (const float*)d_in[3];
    const float* be1 = (const float*)d_in[4];
    const float* w2  = (const float*)d_in[5];
    const float* b2  = (const float*)d_in[6];
    const float* g2  = (const float*)d_in[7];
    const float* be2 = (const float*)d_in[8];
    const float* w3  = (const float*)d_in[9];
    const float* b3  = (const float*)d_in[10];
    const float* g3  = (const float*)d_in[11];
    const float* be3 = (const float*)d_in[12];
    float* out = (float*)d_out;

    cudaFuncSetAttribute(k_fps, cudaFuncAttributeMaxDynamicSharedMemorySize, FPS_SMEM);

    k_xyz4<<<(BB*NN + 255)/256, 256>>>(pts);
    k_fps<<<BB, FPS_THR, FPS_SMEM>>>(pts);
    k_ball<<<(BB*SS)/64, 256>>>();
    k_mlp1<<<MLP_BLOCKS, 256>>>(pts, w1, b1);
    k_stats1<<<1, 32>>>(g1, be1);
    k_mlp2<<<MLP_BLOCKS, 256>>>(w2, b2);
    k_stats2<<<1, 32>>>(g2, be2);
    k_mlp3<<<MLP_BLOCKS, 256>>>(w3, b3);
    k_stats3<<<1, 32>>>(g3, be3);
    k_max<<<(BB*SS*32 + 255)/256, 256>>>(out);
    k_out0<<<(BB*3*SS + 255)/256, 256>>>(out);
}

// round 16
// speedup vs baseline: 2.1277x; 1.2269x over previous
#include <cuda_runtime.h>
#include <cstdint>

#define BB 16
#define NN 16384
#define SS 512
#define NSAMP 16
#define RR2 0.01f
#define NROWS (BB*SS*NSAMP)      // 131072
#define MLP_BLOCKS 512           // NROWS / 256
#define OUT1_OFF (BB*3*SS)       // 24576

#define FPS_THR 512
#define FPS_PAIRS 16             // pairs per thread: 512*16*2 = 16384 points
#define FPS_SMEM (65536*3)       // sx2(64K) + sy2(64K) + sz(64K) = 192 KB

// ---------------- scratch (static device globals; no allocation) -------------
__device__ float4 g_xyz4[BB*NN];          // (x,y,z, x^2+y^2+z^2) - sum NO-FMA
__device__ float4 g_ctr[BB*SS];           // centroid (cx,cy,cz, sn) - sn NO-FMA
__device__ int    g_gidx[BB*SS*NSAMP];
__device__ float  g_y1[NROWS*16];
__device__ float  g_y2[NROWS*16];
__device__ float  g_y3[NROWS*32];
__device__ float  g_part1[MLP_BLOCKS*32];
__device__ float  g_part2[MLP_BLOCKS*32];
__device__ float  g_part3[MLP_BLOCKS*64];
__device__ float  g_scale1[16], g_shift1[16];
__device__ float  g_scale2[16], g_shift2[16];
__device__ float  g_scale3[32], g_shift3[32];

// sum of squares with NO FMA contraction: ((x*x + y*y) + z*z), each op rn
__device__ __forceinline__ float sumsq_nofma(float x, float y, float z) {
    return __fadd_rn(__fadd_rn(__fmul_rn(x, x), __fmul_rn(y, y)), __fmul_rn(z, z));
}

// ---- packed f32x2 helpers (IEEE rn per lane -> bit-identical to scalar) -----
__device__ __forceinline__ unsigned long long pk2(float lo, float hi) {
    unsigned long long r;
    asm("mov.b64 %0, {%1, %2};" : "=l"(r) : "f"(lo), "f"(hi));
    return r;
}
__device__ __forceinline__ void upk2(float& lo, float& hi, unsigned long long v) {
    asm("mov.b64 {%0, %1}, %2;" : "=f"(lo), "=f"(hi) : "l"(v));
}
__device__ __forceinline__ unsigned long long add2(unsigned long long a, unsigned long long b) {
    unsigned long long r;
    asm("add.rn.f32x2 %0, %1, %2;" : "=l"(r) : "l"(a), "l"(b));
    return r;
}
__device__ __forceinline__ unsigned long long mul2(unsigned long long a, unsigned long long b) {
    unsigned long long r;
    asm("mul.rn.f32x2 %0, %1, %2;" : "=l"(r) : "l"(a), "l"(b));
    return r;
}
__device__ __forceinline__ unsigned long long fma2(unsigned long long a, unsigned long long b,
                                                   unsigned long long c) {
    unsigned long long r;
    asm("fma.rn.f32x2 %0, %1, %2, %3;" : "=l"(r) : "l"(a), "l"(b), "l"(c));
    return r;
}

// ---------------- K0: build float4 point array ------------------------------
__global__ void k_xyz4(const float* __restrict__ pts) {
    int t = blockIdx.x * blockDim.x + threadIdx.x;
    if (t >= BB*NN) return;
    int b = t / NN, n = t - b*NN;
    const float* P = pts + (size_t)b*6*NN;
    float x = P[n], y = P[NN+n], z = P[2*NN+n];
    g_xyz4[t] = make_float4(x, y, z, sumsq_nofma(x, y, z));
}

// ---------------- K1: FPS (one CTA per batch, packed f32x2 pairs) ------------
// Each thread owns 16 point-pairs. y,z packed in registers; dist lo/hi in
// registers; x streamed from smem (1 LDS.64/pair). Distance math is the
// packed twin of the bit-exact scalar sequence:
//   dx=FADD(x,-cx); d=FFMA(dz,dz,FFMA(dy,dy,FMUL(dx,dx))); nd=FMNMX(dist,d)
// Argmax: value-only REDUX on bits (dist>=0), deferred index rescan by the
// matching thread(s) + atomicMin (min index == first occurrence, as in jnp
// argmax). Centroid recovered by broadcast LDS from sx2/sy2/sz.
__global__ __launch_bounds__(FPS_THR) void k_fps(const float* __restrict__ pts) {
    extern __shared__ char dyn[];
    float2* sx2 = (float2*)dyn;                  // [8192] x pairs
    float2* sy2 = (float2*)(dyn + 65536);        // [8192] y pairs (lookup)
    float*  sz  = (float*)(dyn + 131072);        // [16384] z      (lookup)
    int b = blockIdx.x;
    const float* P = pts + (size_t)b*6*NN;
    int tid = threadIdx.x;
    int lane = tid & 31, wid = tid >> 5;

    unsigned long long ypk[FPS_PAIRS], zpk[FPS_PAIRS];
    float dlo[FPS_PAIRS], dhi[FPS_PAIRS];
#pragma unroll
    for (int k = 0; k < FPS_PAIRS; k++) {
        int j = tid + (k << 9);                  // pair index
        float x0 = P[2*j],      x1 = P[2*j+1];
        float y0 = P[NN+2*j],   y1 = P[NN+2*j+1];
        float z0 = P[2*NN+2*j], z1 = P[2*NN+2*j+1];
        sx2[j] = make_float2(x0, x1);
        sy2[j] = make_float2(y0, y1);
        sz[2*j] = z0; sz[2*j+1] = z1;
        ypk[k] = pk2(y0, y1);
        zpk[k] = pk2(z0, z1);
        dlo[k] = 1e10f; dhi[k] = 1e10f;
    }

    __shared__ unsigned s_w[16];
    __shared__ unsigned s_wv;
    __shared__ int s_idx[2];

    if (tid == 0) { s_idx[0] = 0x7fffffff; s_idx[1] = 0x7fffffff; }
    __syncthreads();

    // iteration 0: centroid = point 0
    float cx = sx2[0].x, cy = sy2[0].x, cz = sz[0];
    if (tid == 0)
        g_ctr[b*SS] = make_float4(cx, cy, cz, sumsq_nofma(cx, cy, cz));

    for (int t = 1; t < SS; t++) {
        unsigned long long ncx = pk2(-cx, -cx);
        unsigned long long ncy = pk2(-cy, -cy);
        unsigned long long ncz = pk2(-cz, -cz);
        float tl = -1.0f, th = -1.0f;
#pragma unroll
        for (int k = 0; k < FPS_PAIRS; k++) {
            int j = tid + (k << 9);
            unsigned long long xp = *(const unsigned long long*)&sx2[j];   // LDS.64
            unsigned long long dx = add2(xp,     ncx);
            unsigned long long dy = add2(ypk[k], ncy);
            unsigned long long dz = add2(zpk[k], ncz);
            unsigned long long d  = mul2(dx, dx);
            d = fma2(dy, dy, d);
            d = fma2(dz, dz, d);
            float l, h; upk2(l, h, d);
            float nl = fminf(dlo[k], l);
            float nh = fminf(dhi[k], h);
            dlo[k] = nl; dhi[k] = nh;
            tl = fmaxf(tl, nl); th = fmaxf(th, nh);
        }
        float tmax = fmaxf(tl, th);
        unsigned vb = __float_as_uint(tmax);      // dist >= 0: bits monotonic
        unsigned vr = __reduce_max_sync(0xffffffffu, vb);
        if (lane == 0) s_w[wid] = vr;
        __syncthreads();                           // B1
        if (wid == 0) {
            unsigned u = (lane < 16) ? s_w[lane] : 0u;
            u = __reduce_max_sync(0xffffffffu, u);
            if (lane == 0) s_wv = u;
        }
        __syncthreads();                           // B2
        unsigned wv = s_wv;
        int slot = t & 1;
        if (vb == wv) {                            // ~1 thread
            int best = 0x7fffffff;
#pragma unroll
            for (int k = 0; k < FPS_PAIRS; k++) {
                int j2 = 2*(tid + (k << 9));
                if (__float_as_uint(dlo[k]) == wv)      best = min(best, j2);
                else if (__float_as_uint(dhi[k]) == wv) best = min(best, j2+1);
            }
            atomicMin(&s_idx[slot], best);
        }
        __syncthreads();                           // B3
        int far = s_idx[slot];
        if (tid == 0) s_idx[slot^1] = 0x7fffffff;  // safe: last read was iter t-1
        float2 xx = sx2[far >> 1];
        float2 yy = sy2[far >> 1];
        cx = (far & 1) ? xx.y : xx.x;
        cy = (far & 1) ? yy.y : yy.x;
        cz = sz[far];
        if (tid == 0)
            g_ctr[b*SS + t] = make_float4(cx, cy, cz, sumsq_nofma(cx, cy, cz));
    }
}

// ---------------- K2: ball query (one warp per 8 groups) ---------------------
__global__ __launch_bounds__(256) void k_ball() {
    int w    = threadIdx.x >> 5;
    int lane = threadIdx.x & 31;
    int gbase = blockIdx.x * 64 + w * 8;      // 64 groups per block, same batch
    int b = gbase >> 9;

    __shared__ int sbuf[8][8][16];

    float4 c[8]; int cnt[8];
#pragma unroll
    for (int j = 0; j < 8; j++) { c[j] = g_ctr[gbase + j]; cnt[j] = 0; }

    const float4* __restrict__ Q = g_xyz4 + (size_t)b*NN;
    unsigned lmask = (1u << lane) - 1u;

    float4 q = Q[lane];
    for (int n0 = 0; n0 < NN; n0 += 32) {
        float4 qn = Q[(n0 + 32 + lane) & (NN - 1)];
        int n = n0 + lane;
#pragma unroll
        for (int j = 0; j < 8; j++) {
            float d0  = __fmul_rn(c[j].x, q.x);
            float d1  = fmaf(c[j].y, q.y, d0);
            float dot = fmaf(c[j].z, q.z, d1);
            float sq  = __fsub_rn(__fadd_rn(c[j].w, q.w), __fmul_rn(2.0f, dot));
            bool pred = !(sq > RR2);
            unsigned m = __ballot_sync(0xffffffffu, pred);
            if (m) {
                int pos = cnt[j] + __popc(m & lmask);
                if (pred && pos < 16) sbuf[w][j][pos] = n;
                cnt[j] += __popc(m);
            }
        }
        q = qn;
    }
    __syncwarp();
#pragma unroll
    for (int j = 0; j < 8; j++) {
        int cj = cnt[j];
        int first = sbuf[w][j][0];
        if (lane < 16) {
            int v = (lane < cj) ? sbuf[w][j][lane] : first;
            g_gidx[(gbase + j)*16 + lane] = v;
        }
    }
}

// ------------- deterministic per-block stat reduction ------------------------
template<int NCH>
__device__ __forceinline__ void stat_reduce(float* ls, float* lq, float* part) {
    __shared__ float ss[8][NCH], sq2[8][NCH];
    int wid = threadIdx.x >> 5, lane = threadIdx.x & 31;
#pragma unroll
    for (int c = 0; c < NCH; c++) {
        float v = ls[c], q = lq[c];
#pragma unroll
        for (int off = 16; off; off >>= 1) {
            v += __shfl_down_sync(0xffffffffu, v, off);
            q += __shfl_down_sync(0xffffffffu, q, off);
        }
        if (lane == 0) { ss[wid][c] = v; sq2[wid][c] = q; }
    }
    __syncthreads();
    if (threadIdx.x < NCH) {
        float v = 0.f, q = 0.f;
#pragma unroll
        for (int ww = 0; ww < 8; ww++) { v += ss[ww][threadIdx.x]; q += sq2[ww][threadIdx.x]; }
        part[blockIdx.x*(2*NCH) + threadIdx.x]       = v;
        part[blockIdx.x*(2*NCH) + NCH + threadIdx.x] = q;
    }
}

template<int NCH>
__device__ __forceinline__ void stat_final(const float* part, const float* g,
                                           const float* be, float* scale, float* shift) {
    int c = threadIdx.x;
    if (c >= NCH) return;
    float s = 0.f, q = 0.f;
    for (int i = 0; i < MLP_BLOCKS; i++) {
        s += part[i*2*NCH + c];
        q += part[i*2*NCH + NCH + c];
    }
    float inv  = 1.0f / (float)NROWS;
    float mean = s * inv;
    float var  = q * inv - mean*mean;
    float rstd = rsqrtf(var + 1e-5f);
    float a = g[c] * rstd;
    scale[c] = a;
    shift[c] = be[c] - mean * a;
}

// ---------------- K3: gather + linear1 (fp32) + stats ------------------------
__global__ __launch_bounds__(256) void k_mlp1(const float* __restrict__ pts,
                                              const float* __restrict__ w1,
                                              const float* __restrict__ b1) {
    int row = blockIdx.x * 256 + threadIdx.x;   // < NROWS
    int g = row >> 4;
    int b = g >> 9;
    int gi = g_gidx[row];
    gi = min(gi, NN-1);
    float4 p = g_xyz4[(size_t)b*NN + gi];
    float4 c = g_ctr[g];
    const float* PNr = pts + (size_t)b*6*NN + 3*NN;
    float f[6];
    f[0] = p.x - c.x; f[1] = p.y - c.y; f[2] = p.z - c.z;
    f[3] = PNr[gi]; f[4] = PNr[NN+gi]; f[5] = PNr[2*NN+gi];

    float ls[16], lq[16];
    float4* O4 = (float4*)(g_y1 + (size_t)row*16);
#pragma unroll
    for (int o4 = 0; o4 < 4; o4++) {
        float4 yv;
        float* yp = (float*)&yv;
#pragma unroll
        for (int oo = 0; oo < 4; oo++) {
            int o = o4*4 + oo;
            float y = 0.f;
#pragma unroll
            for (int cc = 0; cc < 6; cc++) y = fmaf(f[cc], w1[o*6 + cc], y);
            y += b1[o];
            yp[oo] = y;
            ls[o] = y; lq[o] = y*y;
        }
        O4[o4] = yv;
    }
    stat_reduce<16>(ls, lq, g_part1);
}

__global__ void k_stats1(const float* g, const float* be) {
    stat_final<16>(g_part1, g, be, g_scale1, g_shift1);
}

// ---------------- K4: bnrelu1 + linear2 (fp32) + stats -----------------------
__global__ __launch_bounds__(256) void k_mlp2(const float* __restrict__ w2,
                                              const float* __restrict__ b2) {
    int row = blockIdx.x * 256 + threadIdx.x;
    float h[16];
    const float4* Y4 = (const float4*)(g_y1 + (size_t)row*16);
#pragma unroll
    for (int k4 = 0; k4 < 4; k4++) {
        float4 yv = Y4[k4];
        const float* yp = (const float*)&yv;
#pragma unroll
        for (int kk = 0; kk < 4; kk++) {
            int k = k4*4 + kk;
            h[k] = fmaxf(0.f, yp[kk]*g_scale1[k] + g_shift1[k]);
        }
    }

    float ls[16], lq[16];
    float4* O4 = (float4*)(g_y2 + (size_t)row*16);
#pragma unroll
    for (int o4 = 0; o4 < 4; o4++) {
        float4 yv;
        float* yp = (float*)&yv;
#pragma unroll
        for (int oo = 0; oo < 4; oo++) {
            int o = o4*4 + oo;
            float y = 0.f;
#pragma unroll
            for (int k = 0; k < 16; k++) y = fmaf(h[k], w2[o*16 + k], y);
            y += b2[o];
            yp[oo] = y;
            ls[o] = y; lq[o] = y*y;
        }
        O4[o4] = yv;
    }
    stat_reduce<16>(ls, lq, g_part2);
}

__global__ void k_stats2(const float* g, const float* be) {
    stat_final<16>(g_part2, g, be, g_scale2, g_shift2);
}

// ---------------- K5: bnrelu2 + linear3 (fp32) + stats -----------------------
__global__ __launch_bounds__(256) void k_mlp3(const float* __restrict__ w3,
                                              const float* __restrict__ b3) {
    int row = blockIdx.x * 256 + threadIdx.x;
    float h[16];
    const float4* Y4 = (const float4*)(g_y2 + (size_t)row*16);
#pragma unroll
    for (int k4 = 0; k4 < 4; k4++) {
        float4 yv = Y4[k4];
        const float* yp = (const float*)&yv;
#pragma unroll
        for (int kk = 0; kk < 4; kk++) {
            int k = k4*4 + kk;
            h[k] = fmaxf(0.f, yp[kk]*g_scale2[k] + g_shift2[k]);
        }
    }

    float ls[32], lq[32];
    float4* O4 = (float4*)(g_y3 + (size_t)row*32);
#pragma unroll
    for (int o4 = 0; o4 < 8; o4++) {
        float4 yv;
        float* yp = (float*)&yv;
#pragma unroll
        for (int oo = 0; oo < 4; oo++) {
            int o = o4*4 + oo;
            float y = 0.f;
#pragma unroll
            for (int k = 0; k < 16; k++) y = fmaf(h[k], w3[o*16 + k], y);
            y += b3[o];
            yp[oo] = y;
            ls[o] = y; lq[o] = y*y;
        }
        O4[o4] = yv;
    }
    stat_reduce<32>(ls, lq, g_part3);
}

__global__ void k_stats3(const float* g, const float* be) {
    stat_final<32>(g_part3, g, be, g_scale3, g_shift3);
}

// ---------------- K6: bnrelu3 + max over nsample + transposed store ----------
__global__ void k_max(float* __restrict__ out) {
    int t = blockIdx.x * 256 + threadIdx.x;   // BB*SS*32
    if (t >= BB*SS*32) return;
    int o = t & 31;
    int g = t >> 5;                // b*SS + s
    int b = g >> 9, s = g & 511;
    float a = g_scale3[o], sh = g_shift3[o];
    const float* Y = g_y3 + (size_t)g*16*32 + o;
    float m = 0.0f;                // relu output >= 0
#pragma unroll
    for (int j = 0; j < 16; j++) {
        float h = fmaxf(0.f, Y[j*32]*a + sh);
        m = fmaxf(m, h);
    }
    out[OUT1_OFF + ((b*32 + o) << 9) + s] = m;
}

// ---------------- K7: new_xyz output (B,3,S) ---------------------------------
__global__ void k_out0(float* __restrict__ out) {
    int t = blockIdx.x * 256 + threadIdx.x;   // BB*3*SS
    if (t >= BB*3*SS) return;
    int b = t / (3*SS);
    int r = t - b*3*SS;
    int c = r >> 9, s = r & 511;
    float4 ct = g_ctr[b*SS + s];
    float v = (c == 0) ? ct.x : (c == 1) ? ct.y : ct.z;
    out[t] = v;
}

// ---------------- launcher ---------------------------------------------------
extern "C" void kernel_launch(void* const* d_in, const int* in_sizes, int n_in,
                              void* d_out, int out_size) {
    const float* pts = (const float*)d_in[0];
    const float* w1  = (const float*)d_in[1];
    const float* b1  = (const float*)d_in[2];
    const float* g1  = (const float*)d_in[3];
    const float* be1 = (const float*)d_in[4];
    const float* w2  = (const float*)d_in[5];
    const float* b2  = (const float*)d_in[6];
    const float* g2  = (const float*)d_in[7];
    const float* be2 = (const float*)d_in[8];
    const float* w3  = (const float*)d_in[9];
    const float* b3  = (const float*)d_in[10];
    const float* g3  = (const float*)d_in[11];
    const float* be3 = (const float*)d_in[12];
    float* out = (float*)d_out;

    cudaFuncSetAttribute(k_fps, cudaFuncAttributeMaxDynamicSharedMemorySize, FPS_SMEM);

    k_xyz4<<<(BB*NN + 255)/256, 256>>>(pts);
    k_fps<<<BB, FPS_THR, FPS_SMEM>>>(pts);
    k_ball<<<(BB*SS)/64, 256>>>();
    k_mlp1<<<MLP_BLOCKS, 256>>>(pts, w1, b1);
    k_stats1<<<1, 32>>>(g1, be1);
    k_mlp2<<<MLP_BLOCKS, 256>>>(w2, b2);
    k_stats2<<<1, 32>>>(g2, be2);
    k_mlp3<<<MLP_BLOCKS, 256>>>(w3, b3);
    k_stats3<<<1, 32>>>(g3, be3);
    k_max<<<(BB*SS*32 + 255)/256, 256>>>(out);
    k_out0<<<(BB*3*SS + 255)/256, 256>>>(out);
}